// round 15
// baseline (speedup 1.0000x reference)
#include <cuda_runtime.h>
#include <cuda_fp16.h>
#include <cstdint>
#include <math.h>

// ---------------- problem constants ----------------
#define N_ROWS   2048
#define D_DIM    512
#define C_CLS    100000
#define SCALE_F  30.0f

#define NROWT    16            // 2048/128 row tiles
#define NCT      391           // ceil(100000/256) col tiles
#define TILE_M   128
#define TILE_N   256
#define KC       64            // K per smem tile
#define NKC      8             // 512/64
#define ASTR     72            // padded smem row stride (elems)
#define A_B      (TILE_M*ASTR*2)   // 18432 bytes A per stage
#define B_B      (TILE_N*ASTR*2)   // 36864 bytes B per stage
#define STAGE_B  (A_B + B_B)       // 55296
#define SMEM_BYTES (2*STAGE_B)     // 110592

#define L30 43.2808512266689f        // 30*log2(e)
#define L12 17.312340490667562f      // 12*log2(e)
#define CLIP 0.99999988f             // fp32(1 - 1e-7)

// ---------------- device scratch ----------------
__device__ __align__(128) __half g_An[N_ROWS * D_DIM];
__device__ __align__(128) __half g_Wn[C_CLS * D_DIM];
__device__ float g_psum[(size_t)N_ROWS * NCT];
__device__ float g_gt_logit[N_ROWS];
__device__ float g_nll[N_ROWS];

// ---------------- helpers ----------------
__device__ __forceinline__ uint32_t smem_u32(const void* p) {
    return (uint32_t)__cvta_generic_to_shared(p);
}
__device__ __forceinline__ void cpa16(uint32_t s, const void* g, uint32_t nbytes) {
    asm volatile("cp.async.cg.shared.global [%0], [%1], 16, %2;"
                 :: "r"(s), "l"(g), "r"(nbytes));
}
__device__ __forceinline__ void cpa_commit() {
    asm volatile("cp.async.commit_group;");
}
__device__ __forceinline__ void ldsm4(uint32_t* r, uint32_t a) {
    asm volatile("ldmatrix.sync.aligned.m8n8.x4.shared.b16 {%0,%1,%2,%3}, [%4];"
                 : "=r"(r[0]), "=r"(r[1]), "=r"(r[2]), "=r"(r[3]) : "r"(a));
}
__device__ __forceinline__ void ldsm2(uint32_t* r, uint32_t a) {
    asm volatile("ldmatrix.sync.aligned.m8n8.x2.shared.b16 {%0,%1}, [%2];"
                 : "=r"(r[0]), "=r"(r[1]) : "r"(a));
}
__device__ __forceinline__ void mma_f16(float* c, const uint32_t* a, const uint32_t* b) {
    asm volatile(
        "mma.sync.aligned.m16n8k16.row.col.f32.f16.f16.f32 "
        "{%0,%1,%2,%3}, {%4,%5,%6,%7}, {%8,%9}, {%0,%1,%2,%3};"
        : "+f"(c[0]), "+f"(c[1]), "+f"(c[2]), "+f"(c[3])
        : "r"(a[0]), "r"(a[1]), "r"(a[2]), "r"(a[3]), "r"(b[0]), "r"(b[1]));
}
__device__ __forceinline__ float ex2f(float x) {
    float r;
    asm("ex2.approx.ftz.f32 %0, %1;" : "=f"(r) : "f"(x));
    return r;
}

// ---------------- kernel 1: row-normalize fp32 -> fp16 ----------------
__global__ void norm_rows_kernel(const float* __restrict__ src,
                                 __half* __restrict__ dst, int nrows) {
    int row  = blockIdx.x * (blockDim.x >> 5) + (threadIdx.x >> 5);
    int lane = threadIdx.x & 31;
    if (row >= nrows) return;
    const float* p = src + (size_t)row * D_DIM;
    float x[16];
    float ss = 0.f;
#pragma unroll
    for (int j = 0; j < 16; j++) { x[j] = p[lane + j * 32]; ss += x[j] * x[j]; }
#pragma unroll
    for (int o = 16; o; o >>= 1) ss += __shfl_xor_sync(0xffffffffu, ss, o);
    float inv = 1.0f / fmaxf(sqrtf(ss), 1e-12f);
    __half* q = dst + (size_t)row * D_DIM;
#pragma unroll
    for (int j = 0; j < 16; j++) q[lane + j * 32] = __float2half(x[j] * inv);
}

// ---------------- kernel 1b: exact fp32 gt logit per row ----------------
__global__ void gt_logit_kernel(const float* __restrict__ emb,
                                const float* __restrict__ wgt,
                                const int* __restrict__ gt) {
    int row  = blockIdx.x * 8 + (threadIdx.x >> 5);
    int lane = threadIdx.x & 31;
    if (row >= N_ROWS) return;
    int gi = gt[row];
    gi = gi < 0 ? 0 : (gi >= C_CLS ? C_CLS - 1 : gi);
    const float* a = emb + (size_t)row * D_DIM;
    const float* b = wgt + (size_t)gi * D_DIM;
    float saa = 0.f, sbb = 0.f, sab = 0.f;
#pragma unroll
    for (int j = 0; j < 16; j++) {
        float av = a[lane + j * 32];
        float bv = b[lane + j * 32];
        saa += av * av; sbb += bv * bv; sab += av * bv;
    }
#pragma unroll
    for (int o = 16; o; o >>= 1) {
        saa += __shfl_xor_sync(0xffffffffu, saa, o);
        sbb += __shfl_xor_sync(0xffffffffu, sbb, o);
        sab += __shfl_xor_sync(0xffffffffu, sab, o);
    }
    if (lane == 0) {
        float na = fmaxf(sqrtf(saa), 1e-12f);
        float nb = fmaxf(sqrtf(sbb), 1e-12f);
        float c  = sab / (na * nb);
        c = fminf(fmaxf(c, -CLIP), CLIP);
        g_gt_logit[row] = SCALE_F * c - 12.0f;
    }
}

// ---------------- kernel 2: fused GEMM + partial softmax sums ----------------
// 512 threads = 16 warps: wm = wid&1 (2 x 64 rows), wn = wid>>1 (8 x 32 cols).
// CTA tile 128 x 256; per-warp 64x32 subtile identical to the proven layout.
__global__ __launch_bounds__(512, 1) void cosface_gemm_kernel(
    const int* __restrict__ gt)
{
    extern __shared__ char smem[];
    const uint32_t sbase = smem_u32(smem);
    const int tid  = threadIdx.x;
    const int wid  = tid >> 5;
    const int lane = tid & 31;
    const int wm   = wid & 1;      // 2 warps along M (64 rows each)
    const int wn   = wid >> 1;     // 8 warps along N (32 cols each)

    const int rt = blockIdx.x & (NROWT - 1);
    const int ct = blockIdx.x >> 4;
    const int row0 = rt * TILE_M;
    const int col0 = ct * TILE_N;

    float acc[4][4][4];
#pragma unroll
    for (int i = 0; i < 4; i++)
#pragma unroll
        for (int j = 0; j < 4; j++)
#pragma unroll
            for (int k = 0; k < 4; k++) acc[i][j][k] = 0.f;

    auto load_tile = [&](int kc, int buf) {
        uint32_t sA = sbase + buf * STAGE_B;
        uint32_t sB = sA + A_B;
        // A: 128 rows x 8 segs = 1024 cpa16 ops over 512 threads
#pragma unroll
        for (int i = 0; i < 2; i++) {
            int idx = tid + i * 512;
            int r   = idx >> 3;
            int seg = idx & 7;
            const char* ga = (const char*)g_An +
                ((size_t)(row0 + r) * D_DIM + kc * KC + seg * 8) * 2;
            cpa16(sA + r * (ASTR * 2) + seg * 16, ga, 16);
        }
        // B: 256 rows x 8 segs = 2048 ops
#pragma unroll
        for (int i = 0; i < 4; i++) {
            int idx = tid + i * 512;
            int r   = idx >> 3;
            int seg = idx & 7;
            int crow = col0 + r;
            int cc   = crow < C_CLS ? crow : 0;
            const char* gb = (const char*)g_Wn +
                ((size_t)cc * D_DIM + kc * KC + seg * 8) * 2;
            cpa16(sB + r * (ASTR * 2) + seg * 16, gb, crow < C_CLS ? 16u : 0u);
        }
        cpa_commit();
    };

    load_tile(0, 0);

#pragma unroll 1
    for (int kc = 0; kc < NKC; kc++) {
        int buf = kc & 1;
        if (kc + 1 < NKC) {
            load_tile(kc + 1, buf ^ 1);
            asm volatile("cp.async.wait_group 1;");
        } else {
            asm volatile("cp.async.wait_group 0;");
        }
        __syncthreads();

        uint32_t sA = sbase + buf * STAGE_B;
        uint32_t sB = sA + A_B;
#pragma unroll
        for (int ks = 0; ks < 4; ks++) {
            uint32_t af[4][4], bf[4][2];
#pragma unroll
            for (int mf = 0; mf < 4; mf++) {
                int r = wm * 64 + mf * 16 + (lane & 15);
                int c = ks * 16 + (lane >> 4) * 8;
                ldsm4(af[mf], sA + r * (ASTR * 2) + c * 2);
            }
#pragma unroll
            for (int nf = 0; nf < 4; nf++) {
                int r = wn * 32 + nf * 8 + (lane & 7);
                int c = ks * 16 + ((lane >> 3) & 1) * 8;
                ldsm2(bf[nf], sB + r * (ASTR * 2) + c * 2);
            }
#pragma unroll
            for (int mf = 0; mf < 4; mf++)
#pragma unroll
                for (int nf = 0; nf < 4; nf++)
                    mma_f16(acc[mf][nf], af[mf], bf[nf]);
        }
        __syncthreads();
    }

    // ---- epilogue: clip, exp, per-row partial sums ----
    float* red = (float*)smem;   // 8 warpsN x 128 rows = 4KB (reuses stage 0)
#pragma unroll
    for (int mf = 0; mf < 4; mf++) {
#pragma unroll
        for (int rr = 0; rr < 2; rr++) {
            int rl = wm * 64 + mf * 16 + (lane >> 2) + rr * 8;
            int rg = row0 + rl;
            int gtc = gt[rg];
            float s = 0.f;
#pragma unroll
            for (int nf = 0; nf < 4; nf++) {
#pragma unroll
                for (int e = 0; e < 2; e++) {
                    int cg = col0 + wn * 32 + nf * 8 + (lane & 3) * 2 + e;
                    float v = acc[mf][nf][rr * 2 + e];
                    v = fminf(fmaxf(v, -CLIP), CLIP);
                    float targ = fmaf(v, L30, -L30);   // (30v - 30)*log2e
                    if (cg == gtc) targ -= L12;
                    float t = ex2f(targ);
                    if (cg >= C_CLS) t = 0.f;
                    s += t;
                }
            }
            s += __shfl_xor_sync(0xffffffffu, s, 1);
            s += __shfl_xor_sync(0xffffffffu, s, 2);
            if ((lane & 3) == 0) red[wn * TILE_M + rl] = s;
        }
    }
    __syncthreads();
    if (tid < TILE_M) {
        float s = 0.f;
#pragma unroll
        for (int w = 0; w < 8; w++) s += red[w * TILE_M + tid];
        g_psum[(size_t)(row0 + tid) * NCT + ct] = s;
    }
}

// ---------------- kernel 3: per-row NLL ----------------
__global__ void rownll_kernel() {
    int row  = blockIdx.x * 8 + (threadIdx.x >> 5);
    int lane = threadIdx.x & 31;
    const float* p = g_psum + (size_t)row * NCT;
    float s = 0.f;
    for (int c = lane; c < NCT; c += 32) s += p[c];
#pragma unroll
    for (int o = 16; o; o >>= 1) s += __shfl_xor_sync(0xffffffffu, s, o);
    if (lane == 0) g_nll[row] = SCALE_F + logf(s) - g_gt_logit[row];
}

// ---------------- kernel 4: mean ----------------
__global__ void mean_kernel(float* __restrict__ out) {
    __shared__ float red[1024];
    int tid = threadIdx.x;
    red[tid] = g_nll[tid] + g_nll[tid + 1024];
    __syncthreads();
    for (int o = 512; o; o >>= 1) {
        if (tid < o) red[tid] += red[tid + o];
        __syncthreads();
    }
    if (tid == 0) out[0] = red[0] / (float)N_ROWS;
}

// ---------------- host launcher ----------------
extern "C" void kernel_launch(void* const* d_in, const int* in_sizes, int n_in,
                              void* d_out, int out_size) {
    const float* emb = (const float*)d_in[0];
    const int*   gtp = (const int*)d_in[1];     // ground_truth arrives as int32
    const float* wgt = (const float*)d_in[2];
    float*       out = (float*)d_out;

    void* an_ptr = nullptr;
    void* wn_ptr = nullptr;
    cudaGetSymbolAddress(&an_ptr, g_An);
    cudaGetSymbolAddress(&wn_ptr, g_Wn);

    norm_rows_kernel<<<N_ROWS / 8, 256>>>(emb, (__half*)an_ptr, N_ROWS);
    norm_rows_kernel<<<(C_CLS + 7) / 8, 256>>>(wgt, (__half*)wn_ptr, C_CLS);
    gt_logit_kernel<<<N_ROWS / 8, 256>>>(emb, wgt, gtp);

    cudaFuncSetAttribute(cosface_gemm_kernel,
                         cudaFuncAttributeMaxDynamicSharedMemorySize, SMEM_BYTES);
    cosface_gemm_kernel<<<NROWT * NCT, 512, SMEM_BYTES>>>(gtp);

    rownll_kernel<<<N_ROWS / 8, 256>>>();
    mean_kernel<<<1, 1024>>>(out);
}

// round 17
// speedup vs baseline: 1.1797x; 1.1797x over previous
#include <cuda_runtime.h>
#include <cuda_fp16.h>
#include <cstdint>
#include <math.h>

// ---------------- problem constants ----------------
#define N_ROWS   2048
#define D_DIM    512
#define C_CLS    100000
#define SCALE_F  30.0f

#define NROWT    16            // 2048/128 row tiles
#define NCT      782           // ceil(100000/128) col tiles
#define TILE     128
#define KC       64            // K per smem tile
#define NKC      8             // 512/64
#define ASTR     72            // padded smem row stride (elems)
#define TILE_B   (128*ASTR*2)  // 18432 bytes per tile buffer
#define SMEM_BYTES (4*TILE_B)  // A0 A1 B0 B1 = 73728

#define L30 43.2808512266689f        // 30*log2(e)
#define L12 17.312340490667562f      // 12*log2(e)
#define CLIP 0.99999988f             // fp32(1 - 1e-7)

// prep kernel grid partition
#define NB_E   (N_ROWS/8)            // 256
#define NB_W   (C_CLS/8)             // 12500
#define NB_GT  (N_ROWS/8)            // 256

// ---------------- device scratch ----------------
__device__ __align__(128) __half g_An[N_ROWS * D_DIM];
__device__ __align__(128) __half g_Wn[C_CLS * D_DIM];
__device__ float g_psum[(size_t)N_ROWS * NCT];
__device__ float g_gt_logit[N_ROWS];
__device__ float g_nll[N_ROWS];

// ---------------- helpers ----------------
__device__ __forceinline__ uint32_t smem_u32(const void* p) {
    return (uint32_t)__cvta_generic_to_shared(p);
}
__device__ __forceinline__ void cpa16(uint32_t s, const void* g, uint32_t nbytes) {
    asm volatile("cp.async.cg.shared.global [%0], [%1], 16, %2;"
                 :: "r"(s), "l"(g), "r"(nbytes));
}
__device__ __forceinline__ void cpa_commit() {
    asm volatile("cp.async.commit_group;");
}
__device__ __forceinline__ void ldsm4(uint32_t* r, uint32_t a) {
    asm volatile("ldmatrix.sync.aligned.m8n8.x4.shared.b16 {%0,%1,%2,%3}, [%4];"
                 : "=r"(r[0]), "=r"(r[1]), "=r"(r[2]), "=r"(r[3]) : "r"(a));
}
__device__ __forceinline__ void ldsm2(uint32_t* r, uint32_t a) {
    asm volatile("ldmatrix.sync.aligned.m8n8.x2.shared.b16 {%0,%1}, [%2];"
                 : "=r"(r[0]), "=r"(r[1]) : "r"(a));
}
__device__ __forceinline__ void mma_f16(float* c, const uint32_t* a, const uint32_t* b) {
    asm volatile(
        "mma.sync.aligned.m16n8k16.row.col.f32.f16.f16.f32 "
        "{%0,%1,%2,%3}, {%4,%5,%6,%7}, {%8,%9}, {%0,%1,%2,%3};"
        : "+f"(c[0]), "+f"(c[1]), "+f"(c[2]), "+f"(c[3])
        : "r"(a[0]), "r"(a[1]), "r"(a[2]), "r"(a[3]), "r"(b[0]), "r"(b[1]));
}
__device__ __forceinline__ float ex2f(float x) {
    float r;
    asm("ex2.approx.ftz.f32 %0, %1;" : "=f"(r) : "f"(x));
    return r;
}

// ---------------- device sub-bodies for the merged prep kernel ----------------
__device__ __forceinline__ void norm_one_row(const float* __restrict__ src,
                                             __half* __restrict__ dst,
                                             int row, int lane) {
    const float* p = src + (size_t)row * D_DIM;
    float x[16];
    float ss = 0.f;
#pragma unroll
    for (int j = 0; j < 16; j++) { x[j] = p[lane + j * 32]; ss += x[j] * x[j]; }
#pragma unroll
    for (int o = 16; o; o >>= 1) ss += __shfl_xor_sync(0xffffffffu, ss, o);
    float inv = 1.0f / fmaxf(sqrtf(ss), 1e-12f);
    __half* q = dst + (size_t)row * D_DIM;
#pragma unroll
    for (int j = 0; j < 16; j++) q[lane + j * 32] = __float2half(x[j] * inv);
}

__device__ __forceinline__ void gt_logit_one_row(const float* __restrict__ emb,
                                                 const float* __restrict__ wgt,
                                                 const int* __restrict__ gt,
                                                 int row, int lane) {
    int gi = gt[row];
    gi = gi < 0 ? 0 : (gi >= C_CLS ? C_CLS - 1 : gi);
    const float* a = emb + (size_t)row * D_DIM;
    const float* b = wgt + (size_t)gi * D_DIM;
    float saa = 0.f, sbb = 0.f, sab = 0.f;
#pragma unroll
    for (int j = 0; j < 16; j++) {
        float av = a[lane + j * 32];
        float bv = b[lane + j * 32];
        saa += av * av; sbb += bv * bv; sab += av * bv;
    }
#pragma unroll
    for (int o = 16; o; o >>= 1) {
        saa += __shfl_xor_sync(0xffffffffu, saa, o);
        sbb += __shfl_xor_sync(0xffffffffu, sbb, o);
        sab += __shfl_xor_sync(0xffffffffu, sab, o);
    }
    if (lane == 0) {
        float na = fmaxf(sqrtf(saa), 1e-12f);
        float nb = fmaxf(sqrtf(sbb), 1e-12f);
        float c  = sab / (na * nb);
        c = fminf(fmaxf(c, -CLIP), CLIP);
        g_gt_logit[row] = SCALE_F * c - 12.0f;
    }
}

// ---------------- kernel 1: merged prep (E-norm | W-norm | gt-logit) --------
__global__ void prep_kernel(const float* __restrict__ emb,
                            const float* __restrict__ wgt,
                            const int* __restrict__ gt) {
    int b    = blockIdx.x;
    int warp = threadIdx.x >> 5;
    int lane = threadIdx.x & 31;
    if (b < NB_E) {
        norm_one_row(emb, g_An, b * 8 + warp, lane);
    } else if (b < NB_E + NB_W) {
        norm_one_row(wgt, g_Wn, (b - NB_E) * 8 + warp, lane);
    } else {
        gt_logit_one_row(emb, wgt, gt, (b - NB_E - NB_W) * 8 + warp, lane);
    }
}

// ---------------- kernel 2: fused GEMM + partial softmax sums ----------------
__global__ __launch_bounds__(256, 2) void cosface_gemm_kernel(
    const int* __restrict__ gt)
{
    extern __shared__ char smem[];
    const uint32_t sbase = smem_u32(smem);
    const int tid  = threadIdx.x;
    const int wid  = tid >> 5;
    const int lane = tid & 31;
    const int wm   = wid & 1;      // 2 warps along M (64 rows each)
    const int wn   = wid >> 1;     // 4 warps along N (32 cols each)

    const int rt = blockIdx.x & (NROWT - 1);
    const int ct = blockIdx.x >> 4;
    const int row0 = rt * TILE;
    const int col0 = ct * TILE;

    float acc[4][4][4];
#pragma unroll
    for (int i = 0; i < 4; i++)
#pragma unroll
        for (int j = 0; j < 4; j++)
#pragma unroll
            for (int k = 0; k < 4; k++) acc[i][j][k] = 0.f;

    auto load_tile = [&](int kc, int buf) {
        uint32_t sA = sbase + buf * TILE_B;
        uint32_t sB = sbase + 2 * TILE_B + buf * TILE_B;
#pragma unroll
        for (int i = 0; i < 4; i++) {
            int idx = tid + i * 256;           // 0..1023
            int r   = idx >> 3;
            int seg = idx & 7;
            const char* ga = (const char*)g_An +
                ((size_t)(row0 + r) * D_DIM + kc * KC + seg * 8) * 2;
            cpa16(sA + r * (ASTR * 2) + seg * 16, ga, 16);
            int crow = col0 + r;
            int cc   = crow < C_CLS ? crow : 0;
            const char* gb = (const char*)g_Wn +
                ((size_t)cc * D_DIM + kc * KC + seg * 8) * 2;
            cpa16(sB + r * (ASTR * 2) + seg * 16, gb, crow < C_CLS ? 16u : 0u);
        }
        cpa_commit();
    };

    load_tile(0, 0);

#pragma unroll 1
    for (int kc = 0; kc < NKC; kc++) {
        int buf = kc & 1;
        if (kc + 1 < NKC) {
            load_tile(kc + 1, buf ^ 1);
            asm volatile("cp.async.wait_group 1;");
        } else {
            asm volatile("cp.async.wait_group 0;");
        }
        __syncthreads();

        uint32_t sA = sbase + buf * TILE_B;
        uint32_t sB = sbase + 2 * TILE_B + buf * TILE_B;
#pragma unroll
        for (int ks = 0; ks < 4; ks++) {
            uint32_t af[4][4], bf[4][2];
#pragma unroll
            for (int mf = 0; mf < 4; mf++) {
                int r = wm * 64 + mf * 16 + (lane & 15);
                int c = ks * 16 + (lane >> 4) * 8;
                ldsm4(af[mf], sA + r * (ASTR * 2) + c * 2);
            }
#pragma unroll
            for (int nf = 0; nf < 4; nf++) {
                int r = wn * 32 + nf * 8 + (lane & 7);
                int c = ks * 16 + ((lane >> 3) & 1) * 8;
                ldsm2(bf[nf], sB + r * (ASTR * 2) + c * 2);
            }
#pragma unroll
            for (int mf = 0; mf < 4; mf++)
#pragma unroll
                for (int nf = 0; nf < 4; nf++)
                    mma_f16(acc[mf][nf], af[mf], bf[nf]);
        }
        __syncthreads();
    }

    // ---- epilogue: clip, exp, per-row partial sums ----
    float* red = (float*)smem;   // 4 warpsN x 128 rows (reuses A buf0 region)
#pragma unroll
    for (int mf = 0; mf < 4; mf++) {
#pragma unroll
        for (int rr = 0; rr < 2; rr++) {
            int rl = wm * 64 + mf * 16 + (lane >> 2) + rr * 8;
            int rg = row0 + rl;
            int gtc = gt[rg];
            float s = 0.f;
#pragma unroll
            for (int nf = 0; nf < 4; nf++) {
#pragma unroll
                for (int e = 0; e < 2; e++) {
                    int cg = col0 + wn * 32 + nf * 8 + (lane & 3) * 2 + e;
                    float v = acc[mf][nf][rr * 2 + e];
                    v = fminf(fmaxf(v, -CLIP), CLIP);
                    float targ = fmaf(v, L30, -L30);   // (30v - 30)*log2e
                    if (cg == gtc) targ -= L12;
                    float t = ex2f(targ);
                    if (cg >= C_CLS) t = 0.f;
                    s += t;
                }
            }
            s += __shfl_xor_sync(0xffffffffu, s, 1);
            s += __shfl_xor_sync(0xffffffffu, s, 2);
            if ((lane & 3) == 0) red[wn * TILE + rl] = s;
        }
    }
    __syncthreads();
    if (tid < TILE) {
        float s = red[tid] + red[TILE + tid] + red[2 * TILE + tid] + red[3 * TILE + tid];
        g_psum[(size_t)(row0 + tid) * NCT + ct] = s;
    }
}

// ---------------- kernel 3: per-row NLL ----------------
__global__ void rownll_kernel() {
    int row  = blockIdx.x * 8 + (threadIdx.x >> 5);
    int lane = threadIdx.x & 31;
    const float* p = g_psum + (size_t)row * NCT;
    float s = 0.f;
    for (int c = lane; c < NCT; c += 32) s += p[c];
#pragma unroll
    for (int o = 16; o; o >>= 1) s += __shfl_xor_sync(0xffffffffu, s, o);
    if (lane == 0) g_nll[row] = SCALE_F + logf(s) - g_gt_logit[row];
}

// ---------------- kernel 4: mean ----------------
__global__ void mean_kernel(float* __restrict__ out) {
    __shared__ float red[1024];
    int tid = threadIdx.x;
    red[tid] = g_nll[tid] + g_nll[tid + 1024];
    __syncthreads();
    for (int o = 512; o; o >>= 1) {
        if (tid < o) red[tid] += red[tid + o];
        __syncthreads();
    }
    if (tid == 0) out[0] = red[0] / (float)N_ROWS;
}

// ---------------- host launcher ----------------
extern "C" void kernel_launch(void* const* d_in, const int* in_sizes, int n_in,
                              void* d_out, int out_size) {
    const float* emb = (const float*)d_in[0];
    const int*   gtp = (const int*)d_in[1];     // ground_truth arrives as int32
    const float* wgt = (const float*)d_in[2];
    float*       out = (float*)d_out;

    prep_kernel<<<NB_E + NB_W + NB_GT, 256>>>(emb, wgt, gtp);

    cudaFuncSetAttribute(cosface_gemm_kernel,
                         cudaFuncAttributeMaxDynamicSharedMemorySize, SMEM_BYTES);
    cosface_gemm_kernel<<<NROWT * NCT, 256, SMEM_BYTES>>>(gtp);

    rownll_kernel<<<N_ROWS / 8, 256>>>();
    mean_kernel<<<1, 1024>>>(out);
}